// round 4
// baseline (speedup 1.0000x reference)
#include <cuda_runtime.h>

#define TT 2048
#define BB 32
#define HH 256
#define G3 768
#define NS 1024
#define EMBD 63

// ---------- persistent device scratch (no allocations) ----------
__device__ float d_Eg[2][NS][G3];          // bi + embed @ Wi[1:]
__device__ float d_H[2][TT + 1][BB][HH];   // hidden history, both dirs

// ---------- f32x2 helpers ----------
__device__ __forceinline__ unsigned long long pk2(float a, float b) {
    unsigned long long r;
    asm("mov.b64 %0, {%1, %2};" : "=l"(r) : "f"(a), "f"(b));
    return r;
}
__device__ __forceinline__ void fma2(unsigned long long& d, unsigned long long a,
                                     unsigned long long b) {
    asm("fma.rn.f32x2 %0, %1, %2, %0;" : "+l"(d) : "l"(a), "l"(b));
}
__device__ __forceinline__ float2 up2(unsigned long long v) {
    float lo, hi;
    asm("mov.b64 {%0, %1}, %2;" : "=f"(lo), "=f"(hi) : "l"(v));
    return make_float2(lo, hi);
}
__device__ __forceinline__ unsigned smem_u32(const void* p) {
    unsigned a;
    asm("{ .reg .u64 t; cvta.to.shared.u64 t, %1; cvt.u32.u64 %0, t; }"
        : "=r"(a) : "l"(p));
    return a;
}

// mbarrier: init / remote release-arrive / cluster-acquire parity wait
__device__ __forceinline__ void mbar_init(unsigned addr, unsigned cnt) {
    asm volatile("mbarrier.init.shared.b64 [%0], %1;" :: "r"(addr), "r"(cnt) : "memory");
}
__device__ __forceinline__ void mbar_arrive_peer(unsigned local_addr, unsigned rank) {
    asm volatile(
        "{ .reg .b32 r;\n"
        "  mapa.shared::cluster.u32 r, %0, %1;\n"
        "  mbarrier.arrive.release.cluster.shared::cluster.b64 _, [r]; }"
        :: "r"(local_addr), "r"(rank) : "memory");
}
__device__ __forceinline__ void mbar_wait_parity(unsigned addr, unsigned parity) {
    asm volatile(
        "{ .reg .pred P;\n"
        "WAIT_%=:\n"
        "  mbarrier.try_wait.parity.acquire.cluster.shared::cta.b64 P, [%0], %1, 0x989680;\n"
        "  @P bra.uni DONE_%=;\n"
        "  bra.uni WAIT_%=;\n"
        "DONE_%=: }"
        :: "r"(addr), "r"(parity) : "memory");
}

// =====================================================================
// Kernel A: E[dir] = bi + embed @ Wi[1:, :]
// grid 128, block 256 (8 singers/CTA; thread owns columns c, 256+c, 512+c)
// =====================================================================
__global__ void __launch_bounds__(256) precompute_kernel(
    const float* __restrict__ embed,
    const float* __restrict__ Wif, const float* __restrict__ bif,
    const float* __restrict__ Wib, const float* __restrict__ bib)
{
    const int tid = threadIdx.x;
    __shared__ float emb[8][EMBD];
    const int sb = blockIdx.x * 8;
    for (int i = tid; i < 8 * EMBD; i += 256)
        emb[i / EMBD][i % EMBD] = embed[sb * EMBD + i];
    __syncthreads();

    const int c = tid;
    float af0[8], af1[8], af2[8], ab0[8], ab1[8], ab2[8];
#pragma unroll
    for (int s = 0; s < 8; s++) { af0[s]=af1[s]=af2[s]=ab0[s]=ab1[s]=ab2[s]=0.f; }

    for (int e = 0; e < EMBD; e++) {
        const float wf0 = Wif[(1 + e) * G3 + c];
        const float wf1 = Wif[(1 + e) * G3 + 256 + c];
        const float wf2 = Wif[(1 + e) * G3 + 512 + c];
        const float wb0 = Wib[(1 + e) * G3 + c];
        const float wb1 = Wib[(1 + e) * G3 + 256 + c];
        const float wb2 = Wib[(1 + e) * G3 + 512 + c];
#pragma unroll
        for (int s = 0; s < 8; s++) {
            const float x = emb[s][e];
            af0[s] = fmaf(wf0, x, af0[s]);
            af1[s] = fmaf(wf1, x, af1[s]);
            af2[s] = fmaf(wf2, x, af2[s]);
            ab0[s] = fmaf(wb0, x, ab0[s]);
            ab1[s] = fmaf(wb1, x, ab1[s]);
            ab2[s] = fmaf(wb2, x, ab2[s]);
        }
    }
    const float bf0 = bif[c], bf1 = bif[256 + c], bf2 = bif[512 + c];
    const float bb0 = bib[c], bb1 = bib[256 + c], bb2 = bib[512 + c];
#pragma unroll
    for (int s = 0; s < 8; s++) {
        d_Eg[0][sb + s][c]       = af0[s] + bf0;
        d_Eg[0][sb + s][256 + c] = af1[s] + bf1;
        d_Eg[0][sb + s][512 + c] = af2[s] + bf2;
        d_Eg[1][sb + s][c]       = ab0[s] + bb0;
        d_Eg[1][sb + s][256 + c] = ab1[s] + bb1;
        d_Eg[1][sb + s][512 + c] = ab2[s] + bb2;
    }
}

// =====================================================================
// Kernel B: persistent bidirectional GRU scan, cluster-synced.
// grid 128 = 2 dirs x 8 batch-groups(4) x 8 hidden-slices(32 units)
// cluster = 8 consecutive CTAs = the 8 slice CTAs of one (dir, bg).
// block 384: thread = (c = tid%96 column-of-slice, ks = tid/96 k-split of 64)
// =====================================================================
__global__ void __launch_bounds__(384, 1) gru_scan_kernel(
    const float* __restrict__ dur, const int* __restrict__ sid,
    const float* __restrict__ Whf, const float* __restrict__ Whb,
    const float* __restrict__ bhnf, const float* __restrict__ bhnb,
    const float* __restrict__ Wif, const float* __restrict__ Wib)
{
    __shared__ __align__(16) float hsm[4 * 256];   // h[t] for this group's 4 batches
    __shared__ float psum[16 * 96];                // k-split partials
    __shared__ __align__(8) unsigned long long mbar;

    const int tid = threadIdx.x;
    const int dir = blockIdx.x >> 6;
    const int bg  = (blockIdx.x >> 3) & 7;
    const int hs  = blockIdx.x & 7;                // == cluster rank
    const int u0  = hs * 32;
    const unsigned maddr = smem_u32(&mbar);

    const float* Wh  = dir ? Whb : Whf;
    const float* bhn = dir ? bhnb : bhnf;
    const float* Wi  = dir ? Wib : Wif;
    const float* Egd = &d_Eg[dir][0][0];
    float* H = &d_H[dir][0][0][0];

    if (tid == 0) mbar_init(maddr, 8);

    // load my 96-column Wh slice into registers (loop invariant)
    const int c  = tid % 96;
    const int ks = tid / 96;                       // k range [ks*64, ks*64+64)
    const int gcol = (c / 32) * 256 + u0 + (c % 32);
    unsigned long long wp[32];
#pragma unroll
    for (int i = 0; i < 32; i++)
        wp[i] = pk2(Wh[(ks * 64 + 2 * i) * G3 + gcol],
                    Wh[(ks * 64 + 2 * i + 1) * G3 + gcol]);

    // gate-thread constants (tid < 128: b = tid>>5, u = tid&31)
    const int b = tid >> 5;
    const int u = tid & 31;
    const int gb = bg * 4 + b;
    float wi0r = 0.f, wi0z = 0.f, wi0n = 0.f, bhn_u = 0.f;
    int   sid_cur = 0;
    float dur_cur = 0.f;
    if (tid < 128) {
        wi0r  = Wi[u0 + u];
        wi0z  = Wi[256 + u0 + u];
        wi0n  = Wi[512 + u0 + u];
        bhn_u = bhn[u0 + u];
        const int st = dir ? (TT - 1) : 0;
        sid_cur = sid[gb * TT + st];
        dur_cur = dur[gb * TT + st];
        H[(size_t)gb * HH + u0 + u] = 0.f;         // publish h[0] = 0
    }

    // all peer mbarriers initialized (and h[0] visible) before any remote arrive
    asm volatile("barrier.cluster.arrive.aligned;" ::: "memory");
    asm volatile("barrier.cluster.wait.aligned;" ::: "memory");

    __syncthreads();
    if (tid < 8) mbar_arrive_peer(maddr, (unsigned)tid);   // h[0] ready -> phase 0

    for (int t = 0; t < TT; ++t) {
        // gate-input gathers (independent of recurrence) issued early
        float er = 0.f, ez = 0.f, en = 0.f;
        int sid_nx = 0; float dur_nx = 0.f;
        if (tid < 128) {
            const float* Er = Egd + (size_t)sid_cur * G3;
            er = __ldg(Er + u0 + u);
            ez = __ldg(Er + 256 + u0 + u);
            en = __ldg(Er + 512 + u0 + u);
            if (t + 1 < TT) {
                const int st = dir ? (TT - 2 - t) : (t + 1);
                sid_nx = sid[gb * TT + st];
                dur_nx = dur[gb * TT + st];
            }
        }

        // wait until all 8 slice CTAs published h[t]
        mbar_wait_parity(maddr, t & 1);

        // stage h[t] (4 batches x 256) into smem
        const float* hsrc = H + ((size_t)t * BB + bg * 4) * HH;
        for (int i = tid; i < 1024; i += 384) hsm[i] = __ldcg(hsrc + i);
        __syncthreads();

        // GEMM partial: gh[b][c] over my 64-k slice
        unsigned long long acc[4];
#pragma unroll
        for (int i = 0; i < 4; i++) acc[i] = pk2(0.f, 0.f);
        const float* hbase = hsm + ks * 64;
#pragma unroll
        for (int kk = 0; kk < 64; kk += 4) {
            const unsigned long long w0 = wp[kk >> 1];
            const unsigned long long w1 = wp[(kk >> 1) + 1];
#pragma unroll
            for (int bb2 = 0; bb2 < 4; ++bb2) {
                const ulonglong2 hv =
                    *reinterpret_cast<const ulonglong2*>(hbase + bb2 * 256 + kk);
                fma2(acc[bb2], w0, hv.x);
                fma2(acc[bb2], w1, hv.y);
            }
        }
#pragma unroll
        for (int bb2 = 0; bb2 < 4; ++bb2) {
            const float2 a = up2(acc[bb2]);
            psum[(ks * 4 + bb2) * 96 + c] = a.x + a.y;
        }
        __syncthreads();

        // gates: reduce k-splits directly, update state, publish
        if (tid < 128) {
            float hr = 0.f, hz = 0.f, hn = 0.f;
#pragma unroll
            for (int k2 = 0; k2 < 4; k2++) {
                const int base = (k2 * 4 + b) * 96;
                hr += psum[base + u];
                hz += psum[base + 32 + u];
                hn += psum[base + 64 + u];
            }
            const float hprev = hsm[b * 256 + u0 + u];
            const float ir  = fmaf(dur_cur, wi0r, er);
            const float iz  = fmaf(dur_cur, wi0z, ez);
            const float inn = fmaf(dur_cur, wi0n, en);
            const float r = 1.f / (1.f + __expf(-(ir + hr)));
            const float z = 1.f / (1.f + __expf(-(iz + hz)));
            const float n = tanhf(fmaf(r, hn + bhn_u, inn));
            const float hnew = (1.f - z) * n + z * hprev;
            H[((size_t)(t + 1) * BB + gb) * HH + u0 + u] = hnew;
            sid_cur = sid_nx;
            dur_cur = dur_nx;
        }
        __syncthreads();
        // publish h[t+1]; SKIP on the last iteration — nobody waits on phase TT,
        // and a remote arrive into a peer that may already have exited faults.
        if (t + 1 < TT && tid < 8) mbar_arrive_peer(maddr, (unsigned)tid);
    }

    // lifetime guarantee: no CTA exits while any peer op could target its SMEM
    asm volatile("barrier.cluster.arrive.aligned;" ::: "memory");
    asm volatile("barrier.cluster.wait.aligned;" ::: "memory");
}

// =====================================================================
// Kernel C: out[b,t] = fwd[t+1,b,:].Wd[0:256] + bwd[T-t,b,:].Wd[256:512] + bd
// one warp per (b,t); grid 8192 x 256
// =====================================================================
__global__ void __launch_bounds__(256) out_proj_kernel(
    const float* __restrict__ Wd, const float* __restrict__ bd,
    float* __restrict__ out)
{
    __shared__ float wd[512];
    const int tid = threadIdx.x;
    wd[tid] = Wd[tid];
    wd[tid + 256] = Wd[tid + 256];
    __syncthreads();

    const int warp = tid >> 5, lane = tid & 31;
    const int g = blockIdx.x * 8 + warp;
    const int b = g >> 11;
    const int t = g & 2047;

    const float* hf = &d_H[0][t + 1][b][0];
    const float* hb = &d_H[1][TT - t][b][0];
    float s = 0.f;
#pragma unroll
    for (int i = lane; i < HH; i += 32)
        s = fmaf(hf[i], wd[i], fmaf(hb[i], wd[256 + i], s));
#pragma unroll
    for (int o = 16; o > 0; o >>= 1) s += __shfl_xor_sync(0xffffffffu, s, o);
    if (lane == 0) out[b * TT + t] = s + bd[0];
}

// 4th launch so ncu's "-s 5 -c 1" lands on gru_scan_kernel (index 5 = 2nd B)
__global__ void nop_kernel() {}

// =====================================================================
extern "C" void kernel_launch(void* const* d_in, const int* in_sizes, int n_in,
                              void* d_out, int out_size)
{
    const float* dur   = (const float*)d_in[0];
    const int*   sid   = (const int*)  d_in[1];
    const float* embed = (const float*)d_in[2];
    const float* Wif   = (const float*)d_in[3];
    const float* Whf   = (const float*)d_in[4];
    const float* bif   = (const float*)d_in[5];
    const float* bhnf  = (const float*)d_in[6];
    const float* Wib   = (const float*)d_in[7];
    const float* Whb   = (const float*)d_in[8];
    const float* bib   = (const float*)d_in[9];
    const float* bhnb  = (const float*)d_in[10];
    const float* Wd    = (const float*)d_in[11];
    const float* bd    = (const float*)d_in[12];
    float* out = (float*)d_out;

    precompute_kernel<<<128, 256>>>(embed, Wif, bif, Wib, bib);

    {
        cudaLaunchConfig_t cfg = {};
        cfg.gridDim  = dim3(128, 1, 1);
        cfg.blockDim = dim3(384, 1, 1);
        cfg.dynamicSmemBytes = 0;
        cfg.stream = 0;
        cudaLaunchAttribute attrs[1];
        attrs[0].id = cudaLaunchAttributeClusterDimension;
        attrs[0].val.clusterDim.x = 8;
        attrs[0].val.clusterDim.y = 1;
        attrs[0].val.clusterDim.z = 1;
        cfg.attrs = attrs;
        cfg.numAttrs = 1;
        cudaLaunchKernelEx(&cfg, gru_scan_kernel,
                           dur, sid, Whf, Whb, bhnf, bhnb, Wif, Wib);
    }

    out_proj_kernel<<<8192, 256>>>(Wd, bd, out);
    nop_kernel<<<1, 32>>>();
}

// round 5
// speedup vs baseline: 1.2402x; 1.2402x over previous
#include <cuda_runtime.h>

#define TT 2048
#define BB 32
#define HH 256
#define G3 768
#define NS 1024
#define EMBD 63

// ---------- persistent device scratch (no allocations) ----------
__device__ float d_Eg[2][NS][G3];          // bi + embed @ Wi[1:]
__device__ float d_H[2][TT + 1][BB][HH];   // hidden history, both dirs

// ---------- f32x2 helpers ----------
__device__ __forceinline__ unsigned long long pk2(float a, float b) {
    unsigned long long r;
    asm("mov.b64 %0, {%1, %2};" : "=l"(r) : "f"(a), "f"(b));
    return r;
}
__device__ __forceinline__ void fma2(unsigned long long& d, unsigned long long a,
                                     unsigned long long b) {
    asm("fma.rn.f32x2 %0, %1, %2, %0;" : "+l"(d) : "l"(a), "l"(b));
}
__device__ __forceinline__ float2 up2(unsigned long long v) {
    float lo, hi;
    asm("mov.b64 {%0, %1}, %2;" : "=f"(lo), "=f"(hi) : "l"(v));
    return make_float2(lo, hi);
}
__device__ __forceinline__ unsigned smem_u32(const void* p) {
    unsigned a;
    asm("{ .reg .u64 t; cvta.to.shared.u64 t, %1; cvt.u32.u64 %0, t; }"
        : "=r"(a) : "l"(p));
    return a;
}

// mbarrier helpers
__device__ __forceinline__ void mbar_init(unsigned addr, unsigned cnt) {
    asm volatile("mbarrier.init.shared.b64 [%0], %1;" :: "r"(addr), "r"(cnt) : "memory");
}
__device__ __forceinline__ void mbar_arrive_peer(unsigned local_addr, unsigned rank) {
    asm volatile(
        "{ .reg .b32 r;\n"
        "  mapa.shared::cluster.u32 r, %0, %1;\n"
        "  mbarrier.arrive.release.cluster.shared::cluster.b64 _, [r]; }"
        :: "r"(local_addr), "r"(rank) : "memory");
}
__device__ __forceinline__ void mbar_wait_parity(unsigned addr, unsigned parity) {
    asm volatile(
        "{ .reg .pred P;\n"
        "WAIT_%=:\n"
        "  mbarrier.try_wait.parity.acquire.cluster.shared::cta.b64 P, [%0], %1, 0x989680;\n"
        "  @P bra.uni DONE_%=;\n"
        "  bra.uni WAIT_%=;\n"
        "DONE_%=: }"
        :: "r"(addr), "r"(parity) : "memory");
}
// weak f32 store into a peer CTA's smem (same local offset)
__device__ __forceinline__ void st_peer_f32(unsigned local_addr, unsigned rank, float v) {
    asm volatile(
        "{ .reg .b32 r;\n"
        "  mapa.shared::cluster.u32 r, %0, %1;\n"
        "  st.shared::cluster.f32 [r], %2; }"
        :: "r"(local_addr), "r"(rank), "f"(v) : "memory");
}

// =====================================================================
// Kernel A: E[dir] = bi + embed @ Wi[1:, :]
// =====================================================================
__global__ void __launch_bounds__(256) precompute_kernel(
    const float* __restrict__ embed,
    const float* __restrict__ Wif, const float* __restrict__ bif,
    const float* __restrict__ Wib, const float* __restrict__ bib)
{
    const int tid = threadIdx.x;
    __shared__ float emb[8][EMBD];
    const int sb = blockIdx.x * 8;
    for (int i = tid; i < 8 * EMBD; i += 256)
        emb[i / EMBD][i % EMBD] = embed[sb * EMBD + i];
    __syncthreads();

    const int c = tid;
    float af0[8], af1[8], af2[8], ab0[8], ab1[8], ab2[8];
#pragma unroll
    for (int s = 0; s < 8; s++) { af0[s]=af1[s]=af2[s]=ab0[s]=ab1[s]=ab2[s]=0.f; }

    for (int e = 0; e < EMBD; e++) {
        const float wf0 = Wif[(1 + e) * G3 + c];
        const float wf1 = Wif[(1 + e) * G3 + 256 + c];
        const float wf2 = Wif[(1 + e) * G3 + 512 + c];
        const float wb0 = Wib[(1 + e) * G3 + c];
        const float wb1 = Wib[(1 + e) * G3 + 256 + c];
        const float wb2 = Wib[(1 + e) * G3 + 512 + c];
#pragma unroll
        for (int s = 0; s < 8; s++) {
            const float x = emb[s][e];
            af0[s] = fmaf(wf0, x, af0[s]);
            af1[s] = fmaf(wf1, x, af1[s]);
            af2[s] = fmaf(wf2, x, af2[s]);
            ab0[s] = fmaf(wb0, x, ab0[s]);
            ab1[s] = fmaf(wb1, x, ab1[s]);
            ab2[s] = fmaf(wb2, x, ab2[s]);
        }
    }
    const float bf0 = bif[c], bf1 = bif[256 + c], bf2 = bif[512 + c];
    const float bb0 = bib[c], bb1 = bib[256 + c], bb2 = bib[512 + c];
#pragma unroll
    for (int s = 0; s < 8; s++) {
        d_Eg[0][sb + s][c]       = af0[s] + bf0;
        d_Eg[0][sb + s][256 + c] = af1[s] + bf1;
        d_Eg[0][sb + s][512 + c] = af2[s] + bf2;
        d_Eg[1][sb + s][c]       = ab0[s] + bb0;
        d_Eg[1][sb + s][256 + c] = ab1[s] + bb1;
        d_Eg[1][sb + s][512 + c] = ab2[s] + bb2;
    }
}

// =====================================================================
// Kernel B: persistent bidirectional GRU scan.
// grid 128 = 2 dirs x 8 batch-groups(4 batches) x 8 hidden-slices(32 units)
// cluster = 8 CTAs of one (dir,bg). h exchanged via DSMEM double buffer;
// tid0-only mbarrier wait; hprev register-carried by gate threads.
// =====================================================================
__global__ void __launch_bounds__(384, 1) gru_scan_kernel(
    const float* __restrict__ dur, const int* __restrict__ sid,
    const float* __restrict__ Whf, const float* __restrict__ Whb,
    const float* __restrict__ bhnf, const float* __restrict__ bhnb,
    const float* __restrict__ Wif, const float* __restrict__ Wib)
{
    __shared__ __align__(16) float hsm[2][4 * 256];   // double-buffered h (peer-written)
    __shared__ float psum[16 * 96];
    __shared__ __align__(8) unsigned long long mbar;

    const int tid = threadIdx.x;
    const int dir = blockIdx.x >> 6;
    const int bg  = (blockIdx.x >> 3) & 7;
    const int hs  = blockIdx.x & 7;                   // cluster rank
    const int u0  = hs * 32;
    const unsigned maddr = smem_u32(&mbar);
    const unsigned hsm0  = smem_u32(&hsm[0][0]);

    const float* Wh  = dir ? Whb : Whf;
    const float* bhn = dir ? bhnb : bhnf;
    const float* Wi  = dir ? Wib : Wif;
    const float* Egd = &d_Eg[dir][0][0];
    float* H = &d_H[dir][0][0][0];

    if (tid == 0) mbar_init(maddr, 8);
    for (int i = tid; i < 1024; i += 384) hsm[0][i] = 0.f;   // h[0] = 0

    // my 96-column Wh slice in registers (loop invariant)
    const int c  = tid % 96;
    const int ks = tid / 96;                          // k range [ks*64, ks*64+64)
    const int gcol = (c / 32) * 256 + u0 + (c % 32);
    unsigned long long wp[32];
#pragma unroll
    for (int i = 0; i < 32; i++)
        wp[i] = pk2(Wh[(ks * 64 + 2 * i) * G3 + gcol],
                    Wh[(ks * 64 + 2 * i + 1) * G3 + gcol]);

    // gate-thread state (tid < 128: b = tid>>5, u = tid&31)
    const int b = tid >> 5;
    const int u = tid & 31;
    const int gb = bg * 4 + b;
    const unsigned myoff = (unsigned)(b * 256 + u0 + u) * 4u;  // byte offset in hsm buf
    float wi0r = 0.f, wi0z = 0.f, wi0n = 0.f, bhn_u = 0.f;
    float hprev = 0.f;
    int   sid_cur = 0;
    float dur_cur = 0.f;
    if (tid < 128) {
        wi0r  = Wi[u0 + u];
        wi0z  = Wi[256 + u0 + u];
        wi0n  = Wi[512 + u0 + u];
        bhn_u = bhn[u0 + u];
        const int st = dir ? (TT - 1) : 0;
        sid_cur = sid[gb * TT + st];
        dur_cur = dur[gb * TT + st];
    }

    // all mbarriers init'd + hsm[0] zeroed cluster-wide before use
    __syncthreads();
    asm volatile("barrier.cluster.arrive.aligned;" ::: "memory");
    asm volatile("barrier.cluster.wait.aligned;" ::: "memory");

    for (int t = 0; t < TT; ++t) {
        // gate-input gathers (independent of the recurrence) issued first
        float er = 0.f, ez = 0.f, en = 0.f;
        int sid_nx = 0; float dur_nx = 0.f;
        if (tid < 128) {
            const float* Er = Egd + (size_t)sid_cur * G3;
            er = __ldg(Er + u0 + u);
            ez = __ldg(Er + 256 + u0 + u);
            en = __ldg(Er + 512 + u0 + u);
            if (t + 1 < TT) {
                const int st = dir ? (TT - 2 - t) : (t + 1);
                sid_nx = sid[gb * TT + st];
                dur_nx = dur[gb * TT + st];
            }
        }

        // h[t] already in hsm[t&1] (DSMEM-pushed); tid0 waits, bar broadcasts
        if (t > 0) { if (tid == 0) mbar_wait_parity(maddr, (t - 1) & 1); }
        __syncthreads();

        // GEMM partial: gh[b][c] over my 64-k slice, straight from smem
        const float* hcur = &hsm[t & 1][0];
        unsigned long long acc[4];
#pragma unroll
        for (int i = 0; i < 4; i++) acc[i] = pk2(0.f, 0.f);
        const float* hbase = hcur + ks * 64;
#pragma unroll
        for (int kk = 0; kk < 64; kk += 4) {
            const unsigned long long w0 = wp[kk >> 1];
            const unsigned long long w1 = wp[(kk >> 1) + 1];
#pragma unroll
            for (int bb2 = 0; bb2 < 4; ++bb2) {
                const ulonglong2 hv =
                    *reinterpret_cast<const ulonglong2*>(hbase + bb2 * 256 + kk);
                fma2(acc[bb2], w0, hv.x);
                fma2(acc[bb2], w1, hv.y);
            }
        }
#pragma unroll
        for (int bb2 = 0; bb2 < 4; ++bb2) {
            const float2 a = up2(acc[bb2]);
            psum[(ks * 4 + bb2) * 96 + c] = a.x + a.y;
        }
        __syncthreads();

        // gates: reduce k-splits, update state, publish
        if (tid < 128) {
            float hr = 0.f, hz = 0.f, hn = 0.f;
#pragma unroll
            for (int k2 = 0; k2 < 4; k2++) {
                const int base = (k2 * 4 + b) * 96;
                hr += psum[base + u];
                hz += psum[base + 32 + u];
                hn += psum[base + 64 + u];
            }
            const float ir  = fmaf(dur_cur, wi0r, er);
            const float iz  = fmaf(dur_cur, wi0z, ez);
            const float inn = fmaf(dur_cur, wi0n, en);
            const float r = 1.f / (1.f + __expf(-(ir + hr)));
            const float z = 1.f / (1.f + __expf(-(iz + hz)));
            const float n = tanhf(fmaf(r, hn + bhn_u, inn));
            const float hnew = (1.f - z) * n + z * hprev;
            // history for the output projection (off critical path)
            H[((size_t)(t + 1) * BB + gb) * HH + u0 + u] = hnew;
            // push h[t+1] into every cluster CTA's next buffer (incl. self)
            if (t + 1 < TT) {
                const unsigned dst = hsm0 + (unsigned)(((t + 1) & 1) * 4096) + myoff;
#pragma unroll
                for (unsigned rk = 0; rk < 8; rk++) st_peer_f32(dst, rk, hnew);
            }
            hprev = hnew;
            sid_cur = sid_nx;
            dur_cur = dur_nx;
        }
        __syncthreads();
        if (t + 1 < TT && tid < 8) mbar_arrive_peer(maddr, (unsigned)tid);
    }

    // no CTA exits while a peer op could still target its SMEM
    asm volatile("barrier.cluster.arrive.aligned;" ::: "memory");
    asm volatile("barrier.cluster.wait.aligned;" ::: "memory");
}

// =====================================================================
// Kernel C: out[b,t] = fwd[t+1,b,:].Wd[0:256] + bwd[T-t,b,:].Wd[256:512] + bd
// =====================================================================
__global__ void __launch_bounds__(256) out_proj_kernel(
    const float* __restrict__ Wd, const float* __restrict__ bd,
    float* __restrict__ out)
{
    __shared__ float wd[512];
    const int tid = threadIdx.x;
    wd[tid] = Wd[tid];
    wd[tid + 256] = Wd[tid + 256];
    __syncthreads();

    const int warp = tid >> 5, lane = tid & 31;
    const int g = blockIdx.x * 8 + warp;
    const int b = g >> 11;
    const int t = g & 2047;

    const float* hf = &d_H[0][t + 1][b][0];
    const float* hb = &d_H[1][TT - t][b][0];
    float s = 0.f;
#pragma unroll
    for (int i = lane; i < HH; i += 32)
        s = fmaf(hf[i], wd[i], fmaf(hb[i], wd[256 + i], s));
#pragma unroll
    for (int o = 16; o > 0; o >>= 1) s += __shfl_xor_sync(0xffffffffu, s, o);
    if (lane == 0) out[b * TT + t] = s + bd[0];
}

__global__ void nop_kernel() {}

// =====================================================================
extern "C" void kernel_launch(void* const* d_in, const int* in_sizes, int n_in,
                              void* d_out, int out_size)
{
    const float* dur   = (const float*)d_in[0];
    const int*   sid   = (const int*)  d_in[1];
    const float* embed = (const float*)d_in[2];
    const float* Wif   = (const float*)d_in[3];
    const float* Whf   = (const float*)d_in[4];
    const float* bif   = (const float*)d_in[5];
    const float* bhnf  = (const float*)d_in[6];
    const float* Wib   = (const float*)d_in[7];
    const float* Whb   = (const float*)d_in[8];
    const float* bib   = (const float*)d_in[9];
    const float* bhnb  = (const float*)d_in[10];
    const float* Wd    = (const float*)d_in[11];
    const float* bd    = (const float*)d_in[12];
    float* out = (float*)d_out;

    // R2/R4 evidence: ncu captures the 4th launch — put the scan there.
    precompute_kernel<<<128, 256>>>(embed, Wif, bif, Wib, bib);
    nop_kernel<<<1, 32>>>();
    nop_kernel<<<1, 32>>>();

    {
        cudaLaunchConfig_t cfg = {};
        cfg.gridDim  = dim3(128, 1, 1);
        cfg.blockDim = dim3(384, 1, 1);
        cfg.dynamicSmemBytes = 0;
        cfg.stream = 0;
        cudaLaunchAttribute attrs[1];
        attrs[0].id = cudaLaunchAttributeClusterDimension;
        attrs[0].val.clusterDim.x = 8;
        attrs[0].val.clusterDim.y = 1;
        attrs[0].val.clusterDim.z = 1;
        cfg.attrs = attrs;
        cfg.numAttrs = 1;
        cudaLaunchKernelEx(&cfg, gru_scan_kernel,
                           dur, sid, Whf, Whb, bhnf, bhnb, Wif, Wib);
    }

    out_proj_kernel<<<8192, 256>>>(Wd, bd, out);
}

// round 6
// speedup vs baseline: 1.4406x; 1.1616x over previous
#include <cuda_runtime.h>

#define TT 2048
#define BB 32
#define HH 256
#define G3 768
#define NS 1024
#define EMBD 63

// ---------- persistent device scratch (no allocations) ----------
__device__ float    d_Eg[2][NS][G3];          // bi + embed @ Wi[1:]
__device__ float    d_H[2][TT + 1][BB][HH];   // hidden history, both dirs
__device__ unsigned d_Flag[2][8][8][4];       // (dir, bg, slice, gate-warp) -> last t published

// ---------- f32x2 helpers ----------
__device__ __forceinline__ unsigned long long pk2(float a, float b) {
    unsigned long long r;
    asm("mov.b64 %0, {%1, %2};" : "=l"(r) : "f"(a), "f"(b));
    return r;
}
__device__ __forceinline__ void fma2(unsigned long long& d, unsigned long long a,
                                     unsigned long long b) {
    asm("fma.rn.f32x2 %0, %1, %2, %0;" : "+l"(d) : "l"(a), "l"(b));
}
__device__ __forceinline__ float2 up2(unsigned long long v) {
    float lo, hi;
    asm("mov.b64 {%0, %1}, %2;" : "=f"(lo), "=f"(hi) : "l"(v));
    return make_float2(lo, hi);
}

// =====================================================================
// Kernel A: E[dir] = bi + embed @ Wi[1:, :]; zero the flag words.
// grid 128, block 256 (8 singers/CTA; thread owns columns c, 256+c, 512+c)
// =====================================================================
__global__ void __launch_bounds__(256) precompute_kernel(
    const float* __restrict__ embed,
    const float* __restrict__ Wif, const float* __restrict__ bif,
    const float* __restrict__ Wib, const float* __restrict__ bib)
{
    const int tid = threadIdx.x;
    const int gid = blockIdx.x * 256 + tid;
    if (gid < 2 * 8 * 8 * 4) reinterpret_cast<unsigned*>(d_Flag)[gid] = 0u;

    __shared__ float emb[8][EMBD];
    const int sb = blockIdx.x * 8;
    for (int i = tid; i < 8 * EMBD; i += 256)
        emb[i / EMBD][i % EMBD] = embed[sb * EMBD + i];
    __syncthreads();

    const int c = tid;
    float af0[8], af1[8], af2[8], ab0[8], ab1[8], ab2[8];
#pragma unroll
    for (int s = 0; s < 8; s++) { af0[s]=af1[s]=af2[s]=ab0[s]=ab1[s]=ab2[s]=0.f; }

    for (int e = 0; e < EMBD; e++) {
        const float wf0 = Wif[(1 + e) * G3 + c];
        const float wf1 = Wif[(1 + e) * G3 + 256 + c];
        const float wf2 = Wif[(1 + e) * G3 + 512 + c];
        const float wb0 = Wib[(1 + e) * G3 + c];
        const float wb1 = Wib[(1 + e) * G3 + 256 + c];
        const float wb2 = Wib[(1 + e) * G3 + 512 + c];
#pragma unroll
        for (int s = 0; s < 8; s++) {
            const float x = emb[s][e];
            af0[s] = fmaf(wf0, x, af0[s]);
            af1[s] = fmaf(wf1, x, af1[s]);
            af2[s] = fmaf(wf2, x, af2[s]);
            ab0[s] = fmaf(wb0, x, ab0[s]);
            ab1[s] = fmaf(wb1, x, ab1[s]);
            ab2[s] = fmaf(wb2, x, ab2[s]);
        }
    }
    const float bf0 = bif[c], bf1 = bif[256 + c], bf2 = bif[512 + c];
    const float bb0 = bib[c], bb1 = bib[256 + c], bb2 = bib[512 + c];
#pragma unroll
    for (int s = 0; s < 8; s++) {
        d_Eg[0][sb + s][c]       = af0[s] + bf0;
        d_Eg[0][sb + s][256 + c] = af1[s] + bf1;
        d_Eg[0][sb + s][512 + c] = af2[s] + bf2;
        d_Eg[1][sb + s][c]       = ab0[s] + bb0;
        d_Eg[1][sb + s][256 + c] = ab1[s] + bb1;
        d_Eg[1][sb + s][512 + c] = ab2[s] + bb2;
    }
}

// =====================================================================
// Kernel B: persistent bidirectional GRU scan, global per-warp flags.
// grid 128 = 2 dirs x 8 batch-groups(4 batches) x 8 hidden-slices(32 units)
// block 384: GEMM thread = (c = tid%96 column, ks = tid/96 k-split of 64)
//            gate threads  = tid<128 (warp w = batch w, lane = unit)
//            poll warp     = warp 11 (lane -> one of 32 producer flags)
// =====================================================================
__global__ void __launch_bounds__(384, 1) gru_scan_kernel(
    const float* __restrict__ dur, const int* __restrict__ sid,
    const float* __restrict__ Whf, const float* __restrict__ Whb,
    const float* __restrict__ bhnf, const float* __restrict__ bhnb,
    const float* __restrict__ Wif, const float* __restrict__ Wib)
{
    __shared__ __align__(16) float hsm[4 * 256];   // h[t] for this group's 4 batches
    __shared__ float psum[16 * 96];                // k-split partials

    const int tid = threadIdx.x;
    const int dir = blockIdx.x >> 6;
    const int bg  = (blockIdx.x >> 3) & 7;
    const int hs  = blockIdx.x & 7;
    const int u0  = hs * 32;

    const float* Wh  = dir ? Whb : Whf;
    const float* bhn = dir ? bhnb : bhnf;
    const float* Wi  = dir ? Wib : Wif;
    const float* Egd = &d_Eg[dir][0][0];
    float* H = &d_H[dir][0][0][0];
    unsigned* flags    = &d_Flag[dir][bg][0][0];   // 32 words for this group
    unsigned* myflag   = &d_Flag[dir][bg][hs][0];  // my CTA's 4 (per gate warp)

    // h[0] = 0 locally
    for (int i = tid; i < 1024; i += 384) hsm[i] = 0.f;

    // my 96-column Wh slice in registers (loop invariant)
    const int c  = tid % 96;
    const int ks = tid / 96;                       // k range [ks*64, ks*64+64)
    const int gcol = (c / 32) * 256 + u0 + (c % 32);
    unsigned long long wp[32];
#pragma unroll
    for (int i = 0; i < 32; i++)
        wp[i] = pk2(Wh[(ks * 64 + 2 * i) * G3 + gcol],
                    Wh[(ks * 64 + 2 * i + 1) * G3 + gcol]);

    // gate-thread constants (tid < 128: b = tid>>5 = warp, u = tid&31)
    const int b = tid >> 5;
    const int u = tid & 31;
    const int gb = bg * 4 + b;
    float wi0r = 0.f, wi0z = 0.f, wi0n = 0.f, bhn_u = 0.f;
    int   sid_cur = 0;
    float dur_cur = 0.f;
    if (tid < 128) {
        wi0r  = Wi[u0 + u];
        wi0z  = Wi[256 + u0 + u];
        wi0n  = Wi[512 + u0 + u];
        bhn_u = bhn[u0 + u];
        const int st = dir ? (TT - 1) : 0;
        sid_cur = sid[gb * TT + st];
        dur_cur = dur[gb * TT + st];
    }
    __syncthreads();

    for (int t = 0; t < TT; ++t) {
        // gate-input gathers (independent of recurrence) — overlap with GEMM
        float er = 0.f, ez = 0.f, en = 0.f;
        int sid_nx = 0; float dur_nx = 0.f;
        if (tid < 128) {
            const float* Er = Egd + (size_t)sid_cur * G3;
            er = __ldg(Er + u0 + u);
            ez = __ldg(Er + 256 + u0 + u);
            en = __ldg(Er + 512 + u0 + u);
            if (t + 1 < TT) {
                const int st = dir ? (TT - 2 - t) : (t + 1);
                sid_nx = sid[gb * TT + st];
                dur_nx = dur[gb * TT + st];
            }
        }

        // GEMM partial: gh[b][c] over my 64-k slice (hsm holds h[t])
        unsigned long long acc[4];
#pragma unroll
        for (int i = 0; i < 4; i++) acc[i] = pk2(0.f, 0.f);
        const float* hbase = hsm + ks * 64;
#pragma unroll
        for (int kk = 0; kk < 64; kk += 4) {
            const unsigned long long w0 = wp[kk >> 1];
            const unsigned long long w1 = wp[(kk >> 1) + 1];
#pragma unroll
            for (int bb2 = 0; bb2 < 4; ++bb2) {
                const ulonglong2 hv =
                    *reinterpret_cast<const ulonglong2*>(hbase + bb2 * 256 + kk);
                fma2(acc[bb2], w0, hv.x);
                fma2(acc[bb2], w1, hv.y);
            }
        }
#pragma unroll
        for (int bb2 = 0; bb2 < 4; ++bb2) {
            const float2 a = up2(acc[bb2]);
            psum[(ks * 4 + bb2) * 96 + c] = a.x + a.y;
        }
        __syncthreads();   // bar A: psum complete, hsm reads done

        // gates (tid<128): reduce k-splits, update, publish h + per-warp flag
        if (tid < 128) {
            float hr = 0.f, hz = 0.f, hn = 0.f;
#pragma unroll
            for (int k2 = 0; k2 < 4; k2++) {
                const int base = (k2 * 4 + b) * 96;
                hr += psum[base + u];
                hz += psum[base + 32 + u];
                hn += psum[base + 64 + u];
            }
            const float hprev = hsm[b * 256 + u0 + u];   // before stage overwrites
            const float ir  = fmaf(dur_cur, wi0r, er);
            const float iz  = fmaf(dur_cur, wi0z, ez);
            const float inn = fmaf(dur_cur, wi0n, en);
            const float r = 1.f / (1.f + __expf(-(ir + hr)));
            const float z = 1.f / (1.f + __expf(-(iz + hz)));
            const float n = tanhf(fmaf(r, hn + bhn_u, inn));
            const float hnew = (1.f - z) * n + z * hprev;
            H[((size_t)(t + 1) * BB + gb) * HH + u0 + u] = hnew;  // weak STG
            __syncwarp();
            if (u == 0 && t + 1 < TT)                    // warp's 32 stores done
                asm volatile("st.release.gpu.global.u32 [%0], %1;"
                             :: "l"(myflag + b), "r"((unsigned)(t + 1)) : "memory");
            sid_cur = sid_nx;
            dur_cur = dur_nx;
        }
        // poll warp (warp 11): each lane waits for one producer flag
        if (t + 1 < TT && tid >= 352) {
            const int lane = tid - 352;                  // 0..31 -> (slice, warp)
            unsigned v;
            const unsigned want = (unsigned)(t + 1);
            do {
                asm volatile("ld.acquire.gpu.global.u32 %0, [%1];"
                             : "=r"(v) : "l"(flags + lane));
            } while (v < want);
        }
        __syncthreads();   // bar B: flags seen by poll warp -> h[t+1] visible

        // stage h[t+1]: 1024 floats = 256 float4, one LDG.128 per thread
        if (t + 1 < TT && tid < 256) {
            const float4* src = reinterpret_cast<const float4*>(
                H + ((size_t)(t + 1) * BB + bg * 4) * HH);
            float4 v;
            asm volatile("ld.global.cg.v4.f32 {%0,%1,%2,%3}, [%4];"
                         : "=f"(v.x), "=f"(v.y), "=f"(v.z), "=f"(v.w)
                         : "l"(src + tid));
            reinterpret_cast<float4*>(hsm)[tid] = v;
        }
        __syncthreads();   // bar C: hsm = h[t+1]
    }
}

// =====================================================================
// Kernel C: out[b,t] = fwd[t+1,b,:].Wd[0:256] + bwd[T-t,b,:].Wd[256:512] + bd
// =====================================================================
__global__ void __launch_bounds__(256) out_proj_kernel(
    const float* __restrict__ Wd, const float* __restrict__ bd,
    float* __restrict__ out)
{
    __shared__ float wd[512];
    const int tid = threadIdx.x;
    wd[tid] = Wd[tid];
    wd[tid + 256] = Wd[tid + 256];
    __syncthreads();

    const int warp = tid >> 5, lane = tid & 31;
    const int g = blockIdx.x * 8 + warp;
    const int b = g >> 11;
    const int t = g & 2047;

    const float* hf = &d_H[0][t + 1][b][0];
    const float* hb = &d_H[1][TT - t][b][0];
    float s = 0.f;
#pragma unroll
    for (int i = lane; i < HH; i += 32)
        s = fmaf(hf[i], wd[i], fmaf(hb[i], wd[256 + i], s));
#pragma unroll
    for (int o = 16; o > 0; o >>= 1) s += __shfl_xor_sync(0xffffffffu, s, o);
    if (lane == 0) out[b * TT + t] = s + bd[0];
}

__global__ void nop_kernel() {}

// =====================================================================
extern "C" void kernel_launch(void* const* d_in, const int* in_sizes, int n_in,
                              void* d_out, int out_size)
{
    const float* dur   = (const float*)d_in[0];
    const int*   sid   = (const int*)  d_in[1];
    const float* embed = (const float*)d_in[2];
    const float* Wif   = (const float*)d_in[3];
    const float* Whf   = (const float*)d_in[4];
    const float* bif   = (const float*)d_in[5];
    const float* bhnf  = (const float*)d_in[6];
    const float* Wib   = (const float*)d_in[7];
    const float* Whb   = (const float*)d_in[8];
    const float* bib   = (const float*)d_in[9];
    const float* bhnb  = (const float*)d_in[10];
    const float* Wd    = (const float*)d_in[11];
    const float* bd    = (const float*)d_in[12];
    float* out = (float*)d_out;

    // scan kernel kept as the 4th launch — that's the one ncu captures (R5 evidence)
    precompute_kernel<<<128, 256>>>(embed, Wif, bif, Wib, bib);
    nop_kernel<<<1, 32>>>();
    nop_kernel<<<1, 32>>>();
    gru_scan_kernel<<<128, 384>>>(dur, sid, Whf, Whb, bhnf, bhnb, Wif, Wib);
    out_proj_kernel<<<8192, 256>>>(Wd, bd, out);
}